// round 1
// baseline (speedup 1.0000x reference)
#include <cuda_runtime.h>

// ---------------- problem constants (fixed shapes) ----------------
#define NN   50000    // nodes
#define MM   200000   // incidences
#define EE   10000    // hyperedges
#define DN_  256
#define DHA_ 64
#define DH_  256
#define DIN_ 320      // DHA + DH

#define ROWS 64       // incidence rows per block
#define KB   32       // K-chunk staged in smem

// ---------------- device scratch (no allocations allowed) ----------------
__device__ float g_agg[(size_t)EE * DH_];   // hyperedge accumulator (10.2 MB)
__device__ float g_acc[(size_t)NN * DN_];   // node accumulator (51.2 MB)
__device__ float g_deg[NN];                 // node degree

// =====================================================================
// Kernel 1: node -> hyperedge.
// Per block: 64 incidences. gather x -> GEMM1 -> LN+ReLU -> GEMM2 -> RED agg_e
// thread layout: ty = tid>>5 (0..7) owns rows ty*8..ty*8+7, tx = tid&31 owns
// cols tx*8..tx*8+7.  A-loads broadcast within a warp (ty uniform per warp).
// =====================================================================
__global__ __launch_bounds__(256, 1)
void k_n2e(const float* __restrict__ x,
           const int*   __restrict__ node_ids,
           const int*   __restrict__ he_ids,
           const float* __restrict__ w1, const float* __restrict__ b1,
           const float* __restrict__ lng, const float* __restrict__ lnb,
           const float* __restrict__ w2, const float* __restrict__ b2)
{
    extern __shared__ char smem_raw[];
    float* xs = (float*)smem_raw;          // [64][256]
    float* hs = xs + ROWS * DN_;           // [64][256]
    float* ws = hs + ROWS * DH_;           // [32][256]
    int*   eid_s = (int*)(ws + KB * DH_);  // [64]
    int*   nid_s = eid_s + ROWS;           // [64]

    const int tid = threadIdx.x;
    const int ty = tid >> 5, tx = tid & 31, lane = tid & 31, wrp = tid >> 5;
    const int m0 = blockIdx.x * ROWS;

    if (tid < ROWS) {
        eid_s[tid] = he_ids[m0 + tid];
        nid_s[tid] = node_ids[m0 + tid];
    }
    __syncthreads();

    // gather x rows (float4, coalesced per row)
    for (int i = tid; i < ROWS * (DN_ / 4); i += 256) {
        int r = i >> 6, c4 = i & 63;
        float4 v = __ldg((const float4*)&x[(size_t)nid_s[r] * DN_ + c4 * 4]);
        *(float4*)&xs[r * DN_ + c4 * 4] = v;
    }
    __syncthreads();

    float acc[8][8];

    // ---------------- GEMM1: h = xs @ w1 + b1 ----------------
    {
        float4 bb0 = __ldg((const float4*)&b1[tx * 8]);
        float4 bb1 = __ldg((const float4*)&b1[tx * 8 + 4]);
        #pragma unroll
        for (int r = 0; r < 8; r++) {
            acc[r][0]=bb0.x; acc[r][1]=bb0.y; acc[r][2]=bb0.z; acc[r][3]=bb0.w;
            acc[r][4]=bb1.x; acc[r][5]=bb1.y; acc[r][6]=bb1.z; acc[r][7]=bb1.w;
        }
        for (int kc = 0; kc < DN_ / KB; kc++) {
            for (int i = tid; i < KB * (DH_ / 4); i += 256) {
                int kr = i >> 6, c4 = i & 63;
                *(float4*)&ws[kr * DH_ + c4 * 4] =
                    __ldg((const float4*)&w1[(size_t)(kc * KB + kr) * DH_ + c4 * 4]);
            }
            __syncthreads();
            #pragma unroll 4
            for (int k = 0; k < KB; k++) {
                float a[8];
                #pragma unroll
                for (int r = 0; r < 8; r++) a[r] = xs[(ty * 8 + r) * DN_ + kc * KB + k];
                float4 b0 = *(const float4*)&ws[k * DH_ + tx * 8];
                float4 b1v = *(const float4*)&ws[k * DH_ + tx * 8 + 4];
                #pragma unroll
                for (int r = 0; r < 8; r++) {
                    acc[r][0] += a[r] * b0.x;  acc[r][1] += a[r] * b0.y;
                    acc[r][2] += a[r] * b0.z;  acc[r][3] += a[r] * b0.w;
                    acc[r][4] += a[r] * b1v.x; acc[r][5] += a[r] * b1v.y;
                    acc[r][6] += a[r] * b1v.z; acc[r][7] += a[r] * b1v.w;
                }
            }
            __syncthreads();
        }
        #pragma unroll
        for (int r = 0; r < 8; r++) {
            *(float4*)&hs[(ty * 8 + r) * DH_ + tx * 8]     = make_float4(acc[r][0],acc[r][1],acc[r][2],acc[r][3]);
            *(float4*)&hs[(ty * 8 + r) * DH_ + tx * 8 + 4] = make_float4(acc[r][4],acc[r][5],acc[r][6],acc[r][7]);
        }
    }
    __syncthreads();

    // ---------------- LayerNorm + ReLU (warp per row) ----------------
    for (int rr = wrp * 8; rr < wrp * 8 + 8; rr++) {
        float v[8], s = 0.f, sq = 0.f;
        #pragma unroll
        for (int j = 0; j < 8; j++) {
            v[j] = hs[rr * DH_ + lane + j * 32];
            s += v[j]; sq += v[j] * v[j];
        }
        #pragma unroll
        for (int o = 16; o; o >>= 1) {
            s  += __shfl_xor_sync(0xffffffffu, s, o);
            sq += __shfl_xor_sync(0xffffffffu, sq, o);
        }
        float mu = s * (1.f / DH_);
        float var = sq * (1.f / DH_) - mu * mu;
        float rs = rsqrtf(var + 1e-5f);
        #pragma unroll
        for (int j = 0; j < 8; j++) {
            int c = lane + j * 32;
            float t = (v[j] - mu) * rs * __ldg(&lng[c]) + __ldg(&lnb[c]);
            hs[rr * DH_ + c] = fmaxf(t, 0.f);
        }
    }
    __syncthreads();

    // ---------------- GEMM2: msgs = hs @ w2 + b2 -> RED into g_agg ----------------
    {
        float4 bb0 = __ldg((const float4*)&b2[tx * 8]);
        float4 bb1 = __ldg((const float4*)&b2[tx * 8 + 4]);
        #pragma unroll
        for (int r = 0; r < 8; r++) {
            acc[r][0]=bb0.x; acc[r][1]=bb0.y; acc[r][2]=bb0.z; acc[r][3]=bb0.w;
            acc[r][4]=bb1.x; acc[r][5]=bb1.y; acc[r][6]=bb1.z; acc[r][7]=bb1.w;
        }
        for (int kc = 0; kc < DH_ / KB; kc++) {
            for (int i = tid; i < KB * (DH_ / 4); i += 256) {
                int kr = i >> 6, c4 = i & 63;
                *(float4*)&ws[kr * DH_ + c4 * 4] =
                    __ldg((const float4*)&w2[(size_t)(kc * KB + kr) * DH_ + c4 * 4]);
            }
            __syncthreads();
            #pragma unroll 4
            for (int k = 0; k < KB; k++) {
                float a[8];
                #pragma unroll
                for (int r = 0; r < 8; r++) a[r] = hs[(ty * 8 + r) * DH_ + kc * KB + k];
                float4 b0 = *(const float4*)&ws[k * DH_ + tx * 8];
                float4 b1v = *(const float4*)&ws[k * DH_ + tx * 8 + 4];
                #pragma unroll
                for (int r = 0; r < 8; r++) {
                    acc[r][0] += a[r] * b0.x;  acc[r][1] += a[r] * b0.y;
                    acc[r][2] += a[r] * b0.z;  acc[r][3] += a[r] * b0.w;
                    acc[r][4] += a[r] * b1v.x; acc[r][5] += a[r] * b1v.y;
                    acc[r][6] += a[r] * b1v.z; acc[r][7] += a[r] * b1v.w;
                }
            }
            __syncthreads();
        }
        #pragma unroll
        for (int r = 0; r < 8; r++) {
            int e = eid_s[ty * 8 + r];
            float* dst = &g_agg[(size_t)e * DH_ + tx * 8];
            #pragma unroll
            for (int c = 0; c < 8; c++) atomicAdd(&dst[c], acc[r][c]);
        }
    }
}

// =====================================================================
// Kernel 2: hyperedge -> node.
// gather [he_attr | agg_e/(cnt+eps)] (320 wide) -> GEMM(K=320) -> LN+ReLU
// -> GEMM -> ReLU -> RED into g_acc, count degrees.
// =====================================================================
__global__ __launch_bounds__(256, 1)
void k_e2n(const int*   __restrict__ node_ids,
           const int*   __restrict__ he_ids,
           const float* __restrict__ he_attr,
           const float* __restrict__ he_count,
           const float* __restrict__ w1, const float* __restrict__ b1,
           const float* __restrict__ lng, const float* __restrict__ lnb,
           const float* __restrict__ w2, const float* __restrict__ b2)
{
    extern __shared__ char smem_raw[];
    float* as = (float*)smem_raw;            // [64][320]
    float* gs = as + ROWS * DIN_;            // [64][256]
    float* ws = gs + ROWS * DH_;             // [32][256]
    int*   eid_s = (int*)(ws + KB * DH_);    // [64]
    int*   nid_s = eid_s + ROWS;             // [64]
    float* rc_s  = (float*)(nid_s + ROWS);   // [64]

    const int tid = threadIdx.x;
    const int ty = tid >> 5, tx = tid & 31, lane = tid & 31, wrp = tid >> 5;
    const int m0 = blockIdx.x * ROWS;

    if (tid < ROWS) {
        int e = he_ids[m0 + tid];
        eid_s[tid] = e;
        nid_s[tid] = node_ids[m0 + tid];
        rc_s[tid]  = 1.f / (he_count[e] + 1e-6f);
    }
    __syncthreads();

    // gather he_attr part (64 cols)
    for (int i = tid; i < ROWS * (DHA_ / 4); i += 256) {
        int r = i >> 4, c4 = i & 15;
        float4 v = __ldg((const float4*)&he_attr[(size_t)eid_s[r] * DHA_ + c4 * 4]);
        *(float4*)&as[r * DIN_ + c4 * 4] = v;
    }
    // gather normalized agg part (256 cols)
    for (int i = tid; i < ROWS * (DH_ / 4); i += 256) {
        int r = i >> 6, c4 = i & 63;
        float rc = rc_s[r];
        float4 v = *(const float4*)&g_agg[(size_t)eid_s[r] * DH_ + c4 * 4];
        v.x *= rc; v.y *= rc; v.z *= rc; v.w *= rc;
        *(float4*)&as[r * DIN_ + DHA_ + c4 * 4] = v;
    }
    __syncthreads();

    float acc[8][8];

    // ---------------- GEMM1: g = as @ w1 + b1 (K = 320) ----------------
    {
        float4 bb0 = __ldg((const float4*)&b1[tx * 8]);
        float4 bb1 = __ldg((const float4*)&b1[tx * 8 + 4]);
        #pragma unroll
        for (int r = 0; r < 8; r++) {
            acc[r][0]=bb0.x; acc[r][1]=bb0.y; acc[r][2]=bb0.z; acc[r][3]=bb0.w;
            acc[r][4]=bb1.x; acc[r][5]=bb1.y; acc[r][6]=bb1.z; acc[r][7]=bb1.w;
        }
        for (int kc = 0; kc < DIN_ / KB; kc++) {
            for (int i = tid; i < KB * (DH_ / 4); i += 256) {
                int kr = i >> 6, c4 = i & 63;
                *(float4*)&ws[kr * DH_ + c4 * 4] =
                    __ldg((const float4*)&w1[(size_t)(kc * KB + kr) * DH_ + c4 * 4]);
            }
            __syncthreads();
            #pragma unroll 4
            for (int k = 0; k < KB; k++) {
                float a[8];
                #pragma unroll
                for (int r = 0; r < 8; r++) a[r] = as[(ty * 8 + r) * DIN_ + kc * KB + k];
                float4 b0 = *(const float4*)&ws[k * DH_ + tx * 8];
                float4 b1v = *(const float4*)&ws[k * DH_ + tx * 8 + 4];
                #pragma unroll
                for (int r = 0; r < 8; r++) {
                    acc[r][0] += a[r] * b0.x;  acc[r][1] += a[r] * b0.y;
                    acc[r][2] += a[r] * b0.z;  acc[r][3] += a[r] * b0.w;
                    acc[r][4] += a[r] * b1v.x; acc[r][5] += a[r] * b1v.y;
                    acc[r][6] += a[r] * b1v.z; acc[r][7] += a[r] * b1v.w;
                }
            }
            __syncthreads();
        }
        #pragma unroll
        for (int r = 0; r < 8; r++) {
            *(float4*)&gs[(ty * 8 + r) * DH_ + tx * 8]     = make_float4(acc[r][0],acc[r][1],acc[r][2],acc[r][3]);
            *(float4*)&gs[(ty * 8 + r) * DH_ + tx * 8 + 4] = make_float4(acc[r][4],acc[r][5],acc[r][6],acc[r][7]);
        }
    }
    __syncthreads();

    // ---------------- LayerNorm + ReLU ----------------
    for (int rr = wrp * 8; rr < wrp * 8 + 8; rr++) {
        float v[8], s = 0.f, sq = 0.f;
        #pragma unroll
        for (int j = 0; j < 8; j++) {
            v[j] = gs[rr * DH_ + lane + j * 32];
            s += v[j]; sq += v[j] * v[j];
        }
        #pragma unroll
        for (int o = 16; o; o >>= 1) {
            s  += __shfl_xor_sync(0xffffffffu, s, o);
            sq += __shfl_xor_sync(0xffffffffu, sq, o);
        }
        float mu = s * (1.f / DH_);
        float var = sq * (1.f / DH_) - mu * mu;
        float rs = rsqrtf(var + 1e-5f);
        #pragma unroll
        for (int j = 0; j < 8; j++) {
            int c = lane + j * 32;
            float t = (v[j] - mu) * rs * __ldg(&lng[c]) + __ldg(&lnb[c]);
            gs[rr * DH_ + c] = fmaxf(t, 0.f);
        }
    }
    __syncthreads();

    // ---------------- GEMM2: msg = relu(gs @ w2 + b2) -> RED into g_acc ----------------
    {
        float4 bb0 = __ldg((const float4*)&b2[tx * 8]);
        float4 bb1 = __ldg((const float4*)&b2[tx * 8 + 4]);
        #pragma unroll
        for (int r = 0; r < 8; r++) {
            acc[r][0]=bb0.x; acc[r][1]=bb0.y; acc[r][2]=bb0.z; acc[r][3]=bb0.w;
            acc[r][4]=bb1.x; acc[r][5]=bb1.y; acc[r][6]=bb1.z; acc[r][7]=bb1.w;
        }
        for (int kc = 0; kc < DH_ / KB; kc++) {
            for (int i = tid; i < KB * (DN_ / 4); i += 256) {
                int kr = i >> 6, c4 = i & 63;
                *(float4*)&ws[kr * DN_ + c4 * 4] =
                    __ldg((const float4*)&w2[(size_t)(kc * KB + kr) * DN_ + c4 * 4]);
            }
            __syncthreads();
            #pragma unroll 4
            for (int k = 0; k < KB; k++) {
                float a[8];
                #pragma unroll
                for (int r = 0; r < 8; r++) a[r] = gs[(ty * 8 + r) * DH_ + kc * KB + k];
                float4 b0 = *(const float4*)&ws[k * DN_ + tx * 8];
                float4 b1v = *(const float4*)&ws[k * DN_ + tx * 8 + 4];
                #pragma unroll
                for (int r = 0; r < 8; r++) {
                    acc[r][0] += a[r] * b0.x;  acc[r][1] += a[r] * b0.y;
                    acc[r][2] += a[r] * b0.z;  acc[r][3] += a[r] * b0.w;
                    acc[r][4] += a[r] * b1v.x; acc[r][5] += a[r] * b1v.y;
                    acc[r][6] += a[r] * b1v.z; acc[r][7] += a[r] * b1v.w;
                }
            }
            __syncthreads();
        }
        if (tx == 0) {
            #pragma unroll
            for (int r = 0; r < 8; r++) atomicAdd(&g_deg[nid_s[ty * 8 + r]], 1.f);
        }
        #pragma unroll
        for (int r = 0; r < 8; r++) {
            int n = nid_s[ty * 8 + r];
            float* dst = &g_acc[(size_t)n * DN_ + tx * 8];
            #pragma unroll
            for (int c = 0; c < 8; c++) atomicAdd(&dst[c], fmaxf(acc[r][c], 0.f));
        }
    }
}

// =====================================================================
// Kernel 3: out = x + LN(g_acc / (deg + eps)).  Warp per node row.
// =====================================================================
__global__ __launch_bounds__(256, 4)
void k_final(const float* __restrict__ x,
             const float* __restrict__ lng, const float* __restrict__ lnb,
             float* __restrict__ out)
{
    const int lane = threadIdx.x & 31;
    const int n = blockIdx.x * 8 + (threadIdx.x >> 5);
    if (n >= NN) return;

    float rd = 1.f / (g_deg[n] + 1e-6f);
    float v[8], s = 0.f, sq = 0.f;
    #pragma unroll
    for (int j = 0; j < 8; j++) {
        v[j] = g_acc[(size_t)n * DN_ + lane + j * 32] * rd;
        s += v[j]; sq += v[j] * v[j];
    }
    #pragma unroll
    for (int o = 16; o; o >>= 1) {
        s  += __shfl_xor_sync(0xffffffffu, s, o);
        sq += __shfl_xor_sync(0xffffffffu, sq, o);
    }
    float mu = s * (1.f / DN_);
    float var = sq * (1.f / DN_) - mu * mu;
    float rs = rsqrtf(var + 1e-5f);
    #pragma unroll
    for (int j = 0; j < 8; j++) {
        int c = lane + j * 32;
        float t = (v[j] - mu) * rs * __ldg(&lng[c]) + __ldg(&lnb[c]);
        out[(size_t)n * DN_ + c] = __ldg(&x[(size_t)n * DN_ + c]) + t;
    }
}

// =====================================================================
// launcher
// =====================================================================
extern "C" void kernel_launch(void* const* d_in, const int* in_sizes, int n_in,
                              void* d_out, int out_size)
{
    const float* x        = (const float*)d_in[0];
    const int*   node_ids = (const int*)  d_in[1];
    const int*   he_ids   = (const int*)  d_in[2];
    const float* he_attr  = (const float*)d_in[3];
    const float* he_count = (const float*)d_in[4];
    const float* n2e_w1   = (const float*)d_in[5];
    const float* n2e_b1   = (const float*)d_in[6];
    const float* n2e_lng  = (const float*)d_in[7];
    const float* n2e_lnb  = (const float*)d_in[8];
    const float* n2e_w2   = (const float*)d_in[9];
    const float* n2e_b2   = (const float*)d_in[10];
    const float* e2n_w1   = (const float*)d_in[11];
    const float* e2n_b1   = (const float*)d_in[12];
    const float* e2n_lng  = (const float*)d_in[13];
    const float* e2n_lnb  = (const float*)d_in[14];
    const float* e2n_w2   = (const float*)d_in[15];
    const float* e2n_b2   = (const float*)d_in[16];
    const float* ln_g     = (const float*)d_in[17];
    const float* ln_b     = (const float*)d_in[18];
    float* out = (float*)d_out;

    void *p_agg, *p_acc, *p_deg;
    cudaGetSymbolAddress(&p_agg, g_agg);
    cudaGetSymbolAddress(&p_acc, g_acc);
    cudaGetSymbolAddress(&p_deg, g_deg);
    cudaMemsetAsync(p_agg, 0, sizeof(float) * (size_t)EE * DH_);
    cudaMemsetAsync(p_acc, 0, sizeof(float) * (size_t)NN * DN_);
    cudaMemsetAsync(p_deg, 0, sizeof(float) * NN);

    // dynamic smem sizes
    const int smem1 = (ROWS * DN_ + ROWS * DH_ + KB * DH_) * 4 + 2 * ROWS * 4;         // ~164.4 KB
    const int smem2 = (ROWS * DIN_ + ROWS * DH_ + KB * DH_) * 4 + 3 * ROWS * 4;        // ~181.0 KB
    cudaFuncSetAttribute(k_n2e, cudaFuncAttributeMaxDynamicSharedMemorySize, smem1);
    cudaFuncSetAttribute(k_e2n, cudaFuncAttributeMaxDynamicSharedMemorySize, smem2);

    k_n2e<<<MM / ROWS, 256, smem1>>>(x, node_ids, he_ids,
                                     n2e_w1, n2e_b1, n2e_lng, n2e_lnb, n2e_w2, n2e_b2);
    k_e2n<<<MM / ROWS, 256, smem2>>>(node_ids, he_ids, he_attr, he_count,
                                     e2n_w1, e2n_b1, e2n_lng, e2n_lnb, e2n_w2, e2n_b2);
    k_final<<<(NN + 7) / 8, 256>>>(x, ln_g, ln_b, out);
}

// round 2
// speedup vs baseline: 1.0028x; 1.0028x over previous
#include <cuda_runtime.h>

// ---------------- problem constants (fixed shapes) ----------------
#define NN   50000    // nodes
#define MM   200000   // incidences
#define EE   10000    // hyperedges
#define DN_  256
#define DHA_ 64
#define DH_  256
#define DIN_ 320      // DHA + DH

#define ROWS 64       // incidence rows per block
#define KB   32       // K-chunk staged in smem

// ---------------- device scratch (no allocations allowed) ----------------
__device__ float g_agg[(size_t)EE * DH_];   // hyperedge accumulator (10.2 MB)
__device__ float g_acc[(size_t)NN * DN_];   // node accumulator (51.2 MB)
__device__ float g_deg[NN];                 // node degree

// =====================================================================
// Kernel 1: node -> hyperedge.
// Per block: 64 incidences. gather x -> GEMM1 -> LN+ReLU -> GEMM2 -> RED agg_e
// thread layout: ty = tid>>5 (0..7) owns rows ty*8..ty*8+7, tx = tid&31 owns
// cols tx*8..tx*8+7.  A-loads broadcast within a warp (ty uniform per warp).
// =====================================================================
__global__ __launch_bounds__(256, 1)
void k_n2e(const float* __restrict__ x,
           const int*   __restrict__ node_ids,
           const int*   __restrict__ he_ids,
           const float* __restrict__ w1, const float* __restrict__ b1,
           const float* __restrict__ lng, const float* __restrict__ lnb,
           const float* __restrict__ w2, const float* __restrict__ b2)
{
    extern __shared__ char smem_raw[];
    float* xs = (float*)smem_raw;          // [64][256]
    float* hs = xs + ROWS * DN_;           // [64][256]
    float* ws = hs + ROWS * DH_;           // [32][256]
    int*   eid_s = (int*)(ws + KB * DH_);  // [64]
    int*   nid_s = eid_s + ROWS;           // [64]

    const int tid = threadIdx.x;
    const int ty = tid >> 5, tx = tid & 31, lane = tid & 31, wrp = tid >> 5;
    const int m0 = blockIdx.x * ROWS;

    if (tid < ROWS) {
        eid_s[tid] = he_ids[m0 + tid];
        nid_s[tid] = node_ids[m0 + tid];
    }
    __syncthreads();

    // gather x rows (float4, coalesced per row)
    for (int i = tid; i < ROWS * (DN_ / 4); i += 256) {
        int r = i >> 6, c4 = i & 63;
        float4 v = __ldg((const float4*)&x[(size_t)nid_s[r] * DN_ + c4 * 4]);
        *(float4*)&xs[r * DN_ + c4 * 4] = v;
    }
    __syncthreads();

    float acc[8][8];

    // ---------------- GEMM1: h = xs @ w1 + b1 ----------------
    {
        float4 bb0 = __ldg((const float4*)&b1[tx * 8]);
        float4 bb1 = __ldg((const float4*)&b1[tx * 8 + 4]);
        #pragma unroll
        for (int r = 0; r < 8; r++) {
            acc[r][0]=bb0.x; acc[r][1]=bb0.y; acc[r][2]=bb0.z; acc[r][3]=bb0.w;
            acc[r][4]=bb1.x; acc[r][5]=bb1.y; acc[r][6]=bb1.z; acc[r][7]=bb1.w;
        }
        for (int kc = 0; kc < DN_ / KB; kc++) {
            for (int i = tid; i < KB * (DH_ / 4); i += 256) {
                int kr = i >> 6, c4 = i & 63;
                *(float4*)&ws[kr * DH_ + c4 * 4] =
                    __ldg((const float4*)&w1[(size_t)(kc * KB + kr) * DH_ + c4 * 4]);
            }
            __syncthreads();
            #pragma unroll 4
            for (int k = 0; k < KB; k++) {
                float a[8];
                #pragma unroll
                for (int r = 0; r < 8; r++) a[r] = xs[(ty * 8 + r) * DN_ + kc * KB + k];
                float4 b0 = *(const float4*)&ws[k * DH_ + tx * 8];
                float4 b1v = *(const float4*)&ws[k * DH_ + tx * 8 + 4];
                #pragma unroll
                for (int r = 0; r < 8; r++) {
                    acc[r][0] += a[r] * b0.x;  acc[r][1] += a[r] * b0.y;
                    acc[r][2] += a[r] * b0.z;  acc[r][3] += a[r] * b0.w;
                    acc[r][4] += a[r] * b1v.x; acc[r][5] += a[r] * b1v.y;
                    acc[r][6] += a[r] * b1v.z; acc[r][7] += a[r] * b1v.w;
                }
            }
            __syncthreads();
        }
        #pragma unroll
        for (int r = 0; r < 8; r++) {
            *(float4*)&hs[(ty * 8 + r) * DH_ + tx * 8]     = make_float4(acc[r][0],acc[r][1],acc[r][2],acc[r][3]);
            *(float4*)&hs[(ty * 8 + r) * DH_ + tx * 8 + 4] = make_float4(acc[r][4],acc[r][5],acc[r][6],acc[r][7]);
        }
    }
    __syncthreads();

    // ---------------- LayerNorm + ReLU (warp per row) ----------------
    for (int rr = wrp * 8; rr < wrp * 8 + 8; rr++) {
        float v[8], s = 0.f, sq = 0.f;
        #pragma unroll
        for (int j = 0; j < 8; j++) {
            v[j] = hs[rr * DH_ + lane + j * 32];
            s += v[j]; sq += v[j] * v[j];
        }
        #pragma unroll
        for (int o = 16; o; o >>= 1) {
            s  += __shfl_xor_sync(0xffffffffu, s, o);
            sq += __shfl_xor_sync(0xffffffffu, sq, o);
        }
        float mu = s * (1.f / DH_);
        float var = sq * (1.f / DH_) - mu * mu;
        float rs = rsqrtf(var + 1e-5f);
        #pragma unroll
        for (int j = 0; j < 8; j++) {
            int c = lane + j * 32;
            float t = (v[j] - mu) * rs * __ldg(&lng[c]) + __ldg(&lnb[c]);
            hs[rr * DH_ + c] = fmaxf(t, 0.f);
        }
    }
    __syncthreads();

    // ---------------- GEMM2: msgs = hs @ w2 + b2 -> RED into g_agg ----------------
    {
        float4 bb0 = __ldg((const float4*)&b2[tx * 8]);
        float4 bb1 = __ldg((const float4*)&b2[tx * 8 + 4]);
        #pragma unroll
        for (int r = 0; r < 8; r++) {
            acc[r][0]=bb0.x; acc[r][1]=bb0.y; acc[r][2]=bb0.z; acc[r][3]=bb0.w;
            acc[r][4]=bb1.x; acc[r][5]=bb1.y; acc[r][6]=bb1.z; acc[r][7]=bb1.w;
        }
        for (int kc = 0; kc < DH_ / KB; kc++) {
            for (int i = tid; i < KB * (DH_ / 4); i += 256) {
                int kr = i >> 6, c4 = i & 63;
                *(float4*)&ws[kr * DH_ + c4 * 4] =
                    __ldg((const float4*)&w2[(size_t)(kc * KB + kr) * DH_ + c4 * 4]);
            }
            __syncthreads();
            #pragma unroll 4
            for (int k = 0; k < KB; k++) {
                float a[8];
                #pragma unroll
                for (int r = 0; r < 8; r++) a[r] = hs[(ty * 8 + r) * DH_ + kc * KB + k];
                float4 b0 = *(const float4*)&ws[k * DH_ + tx * 8];
                float4 b1v = *(const float4*)&ws[k * DH_ + tx * 8 + 4];
                #pragma unroll
                for (int r = 0; r < 8; r++) {
                    acc[r][0] += a[r] * b0.x;  acc[r][1] += a[r] * b0.y;
                    acc[r][2] += a[r] * b0.z;  acc[r][3] += a[r] * b0.w;
                    acc[r][4] += a[r] * b1v.x; acc[r][5] += a[r] * b1v.y;
                    acc[r][6] += a[r] * b1v.z; acc[r][7] += a[r] * b1v.w;
                }
            }
            __syncthreads();
        }
        #pragma unroll
        for (int r = 0; r < 8; r++) {
            int e = eid_s[ty * 8 + r];
            float* dst = &g_agg[(size_t)e * DH_ + tx * 8];
            #pragma unroll
            for (int c = 0; c < 8; c++) atomicAdd(&dst[c], acc[r][c]);
        }
    }
}

// =====================================================================
// Kernel 2: hyperedge -> node.
// gather [he_attr | agg_e/(cnt+eps)] (320 wide) -> GEMM(K=320) -> LN+ReLU
// -> GEMM -> ReLU -> RED into g_acc, count degrees.
// =====================================================================
__global__ __launch_bounds__(256, 1)
void k_e2n(const int*   __restrict__ node_ids,
           const int*   __restrict__ he_ids,
           const float* __restrict__ he_attr,
           const float* __restrict__ he_count,
           const float* __restrict__ w1, const float* __restrict__ b1,
           const float* __restrict__ lng, const float* __restrict__ lnb,
           const float* __restrict__ w2, const float* __restrict__ b2)
{
    extern __shared__ char smem_raw[];
    float* as = (float*)smem_raw;            // [64][320]
    float* gs = as + ROWS * DIN_;            // [64][256]
    float* ws = gs + ROWS * DH_;             // [32][256]
    int*   eid_s = (int*)(ws + KB * DH_);    // [64]
    int*   nid_s = eid_s + ROWS;             // [64]
    float* rc_s  = (float*)(nid_s + ROWS);   // [64]

    const int tid = threadIdx.x;
    const int ty = tid >> 5, tx = tid & 31, lane = tid & 31, wrp = tid >> 5;
    const int m0 = blockIdx.x * ROWS;

    if (tid < ROWS) {
        int e = he_ids[m0 + tid];
        eid_s[tid] = e;
        nid_s[tid] = node_ids[m0 + tid];
        rc_s[tid]  = 1.f / (he_count[e] + 1e-6f);
    }
    __syncthreads();

    // gather he_attr part (64 cols)
    for (int i = tid; i < ROWS * (DHA_ / 4); i += 256) {
        int r = i >> 4, c4 = i & 15;
        float4 v = __ldg((const float4*)&he_attr[(size_t)eid_s[r] * DHA_ + c4 * 4]);
        *(float4*)&as[r * DIN_ + c4 * 4] = v;
    }
    // gather normalized agg part (256 cols)
    for (int i = tid; i < ROWS * (DH_ / 4); i += 256) {
        int r = i >> 6, c4 = i & 63;
        float rc = rc_s[r];
        float4 v = *(const float4*)&g_agg[(size_t)eid_s[r] * DH_ + c4 * 4];
        v.x *= rc; v.y *= rc; v.z *= rc; v.w *= rc;
        *(float4*)&as[r * DIN_ + DHA_ + c4 * 4] = v;
    }
    __syncthreads();

    float acc[8][8];

    // ---------------- GEMM1: g = as @ w1 + b1 (K = 320) ----------------
    {
        float4 bb0 = __ldg((const float4*)&b1[tx * 8]);
        float4 bb1 = __ldg((const float4*)&b1[tx * 8 + 4]);
        #pragma unroll
        for (int r = 0; r < 8; r++) {
            acc[r][0]=bb0.x; acc[r][1]=bb0.y; acc[r][2]=bb0.z; acc[r][3]=bb0.w;
            acc[r][4]=bb1.x; acc[r][5]=bb1.y; acc[r][6]=bb1.z; acc[r][7]=bb1.w;
        }
        for (int kc = 0; kc < DIN_ / KB; kc++) {
            for (int i = tid; i < KB * (DH_ / 4); i += 256) {
                int kr = i >> 6, c4 = i & 63;
                *(float4*)&ws[kr * DH_ + c4 * 4] =
                    __ldg((const float4*)&w1[(size_t)(kc * KB + kr) * DH_ + c4 * 4]);
            }
            __syncthreads();
            #pragma unroll 4
            for (int k = 0; k < KB; k++) {
                float a[8];
                #pragma unroll
                for (int r = 0; r < 8; r++) a[r] = as[(ty * 8 + r) * DIN_ + kc * KB + k];
                float4 b0 = *(const float4*)&ws[k * DH_ + tx * 8];
                float4 b1v = *(const float4*)&ws[k * DH_ + tx * 8 + 4];
                #pragma unroll
                for (int r = 0; r < 8; r++) {
                    acc[r][0] += a[r] * b0.x;  acc[r][1] += a[r] * b0.y;
                    acc[r][2] += a[r] * b0.z;  acc[r][3] += a[r] * b0.w;
                    acc[r][4] += a[r] * b1v.x; acc[r][5] += a[r] * b1v.y;
                    acc[r][6] += a[r] * b1v.z; acc[r][7] += a[r] * b1v.w;
                }
            }
            __syncthreads();
        }
        #pragma unroll
        for (int r = 0; r < 8; r++) {
            *(float4*)&gs[(ty * 8 + r) * DH_ + tx * 8]     = make_float4(acc[r][0],acc[r][1],acc[r][2],acc[r][3]);
            *(float4*)&gs[(ty * 8 + r) * DH_ + tx * 8 + 4] = make_float4(acc[r][4],acc[r][5],acc[r][6],acc[r][7]);
        }
    }
    __syncthreads();

    // ---------------- LayerNorm + ReLU ----------------
    for (int rr = wrp * 8; rr < wrp * 8 + 8; rr++) {
        float v[8], s = 0.f, sq = 0.f;
        #pragma unroll
        for (int j = 0; j < 8; j++) {
            v[j] = gs[rr * DH_ + lane + j * 32];
            s += v[j]; sq += v[j] * v[j];
        }
        #pragma unroll
        for (int o = 16; o; o >>= 1) {
            s  += __shfl_xor_sync(0xffffffffu, s, o);
            sq += __shfl_xor_sync(0xffffffffu, sq, o);
        }
        float mu = s * (1.f / DH_);
        float var = sq * (1.f / DH_) - mu * mu;
        float rs = rsqrtf(var + 1e-5f);
        #pragma unroll
        for (int j = 0; j < 8; j++) {
            int c = lane + j * 32;
            float t = (v[j] - mu) * rs * __ldg(&lng[c]) + __ldg(&lnb[c]);
            gs[rr * DH_ + c] = fmaxf(t, 0.f);
        }
    }
    __syncthreads();

    // ---------------- GEMM2: msg = relu(gs @ w2 + b2) -> RED into g_acc ----------------
    {
        float4 bb0 = __ldg((const float4*)&b2[tx * 8]);
        float4 bb1 = __ldg((const float4*)&b2[tx * 8 + 4]);
        #pragma unroll
        for (int r = 0; r < 8; r++) {
            acc[r][0]=bb0.x; acc[r][1]=bb0.y; acc[r][2]=bb0.z; acc[r][3]=bb0.w;
            acc[r][4]=bb1.x; acc[r][5]=bb1.y; acc[r][6]=bb1.z; acc[r][7]=bb1.w;
        }
        for (int kc = 0; kc < DH_ / KB; kc++) {
            for (int i = tid; i < KB * (DN_ / 4); i += 256) {
                int kr = i >> 6, c4 = i & 63;
                *(float4*)&ws[kr * DN_ + c4 * 4] =
                    __ldg((const float4*)&w2[(size_t)(kc * KB + kr) * DN_ + c4 * 4]);
            }
            __syncthreads();
            #pragma unroll 4
            for (int k = 0; k < KB; k++) {
                float a[8];
                #pragma unroll
                for (int r = 0; r < 8; r++) a[r] = gs[(ty * 8 + r) * DH_ + kc * KB + k];
                float4 b0 = *(const float4*)&ws[k * DN_ + tx * 8];
                float4 b1v = *(const float4*)&ws[k * DN_ + tx * 8 + 4];
                #pragma unroll
                for (int r = 0; r < 8; r++) {
                    acc[r][0] += a[r] * b0.x;  acc[r][1] += a[r] * b0.y;
                    acc[r][2] += a[r] * b0.z;  acc[r][3] += a[r] * b0.w;
                    acc[r][4] += a[r] * b1v.x; acc[r][5] += a[r] * b1v.y;
                    acc[r][6] += a[r] * b1v.z; acc[r][7] += a[r] * b1v.w;
                }
            }
            __syncthreads();
        }
        if (tx == 0) {
            #pragma unroll
            for (int r = 0; r < 8; r++) atomicAdd(&g_deg[nid_s[ty * 8 + r]], 1.f);
        }
        #pragma unroll
        for (int r = 0; r < 8; r++) {
            int n = nid_s[ty * 8 + r];
            float* dst = &g_acc[(size_t)n * DN_ + tx * 8];
            #pragma unroll
            for (int c = 0; c < 8; c++) atomicAdd(&dst[c], fmaxf(acc[r][c], 0.f));
        }
    }
}

// =====================================================================
// Kernel 3: out = x + LN(g_acc / (deg + eps)).  Warp per node row.
// =====================================================================
__global__ __launch_bounds__(256, 4)
void k_final(const float* __restrict__ x,
             const float* __restrict__ lng, const float* __restrict__ lnb,
             float* __restrict__ out)
{
    const int lane = threadIdx.x & 31;
    const int n = blockIdx.x * 8 + (threadIdx.x >> 5);
    if (n >= NN) return;

    float rd = 1.f / (g_deg[n] + 1e-6f);
    float v[8], s = 0.f, sq = 0.f;
    #pragma unroll
    for (int j = 0; j < 8; j++) {
        v[j] = g_acc[(size_t)n * DN_ + lane + j * 32] * rd;
        s += v[j]; sq += v[j] * v[j];
    }
    #pragma unroll
    for (int o = 16; o; o >>= 1) {
        s  += __shfl_xor_sync(0xffffffffu, s, o);
        sq += __shfl_xor_sync(0xffffffffu, sq, o);
    }
    float mu = s * (1.f / DN_);
    float var = sq * (1.f / DN_) - mu * mu;
    float rs = rsqrtf(var + 1e-5f);
    #pragma unroll
    for (int j = 0; j < 8; j++) {
        int c = lane + j * 32;
        float t = (v[j] - mu) * rs * __ldg(&lng[c]) + __ldg(&lnb[c]);
        out[(size_t)n * DN_ + c] = __ldg(&x[(size_t)n * DN_ + c]) + t;
    }
}

// =====================================================================
// launcher
// =====================================================================
extern "C" void kernel_launch(void* const* d_in, const int* in_sizes, int n_in,
                              void* d_out, int out_size)
{
    const float* x        = (const float*)d_in[0];
    const int*   node_ids = (const int*)  d_in[1];
    const int*   he_ids   = (const int*)  d_in[2];
    const float* he_attr  = (const float*)d_in[3];
    const float* he_count = (const float*)d_in[4];
    const float* n2e_w1   = (const float*)d_in[5];
    const float* n2e_b1   = (const float*)d_in[6];
    const float* n2e_lng  = (const float*)d_in[7];
    const float* n2e_lnb  = (const float*)d_in[8];
    const float* n2e_w2   = (const float*)d_in[9];
    const float* n2e_b2   = (const float*)d_in[10];
    const float* e2n_w1   = (const float*)d_in[11];
    const float* e2n_b1   = (const float*)d_in[12];
    const float* e2n_lng  = (const float*)d_in[13];
    const float* e2n_lnb  = (const float*)d_in[14];
    const float* e2n_w2   = (const float*)d_in[15];
    const float* e2n_b2   = (const float*)d_in[16];
    const float* ln_g     = (const float*)d_in[17];
    const float* ln_b     = (const float*)d_in[18];
    float* out = (float*)d_out;

    void *p_agg, *p_acc, *p_deg;
    cudaGetSymbolAddress(&p_agg, g_agg);
    cudaGetSymbolAddress(&p_acc, g_acc);
    cudaGetSymbolAddress(&p_deg, g_deg);
    cudaMemsetAsync(p_agg, 0, sizeof(float) * (size_t)EE * DH_);
    cudaMemsetAsync(p_acc, 0, sizeof(float) * (size_t)NN * DN_);
    cudaMemsetAsync(p_deg, 0, sizeof(float) * NN);

    // dynamic smem sizes
    const int smem1 = (ROWS * DN_ + ROWS * DH_ + KB * DH_) * 4 + 2 * ROWS * 4;         // ~164.4 KB
    const int smem2 = (ROWS * DIN_ + ROWS * DH_ + KB * DH_) * 4 + 3 * ROWS * 4;        // ~181.0 KB
    cudaFuncSetAttribute(k_n2e, cudaFuncAttributeMaxDynamicSharedMemorySize, smem1);
    cudaFuncSetAttribute(k_e2n, cudaFuncAttributeMaxDynamicSharedMemorySize, smem2);

    k_n2e<<<MM / ROWS, 256, smem1>>>(x, node_ids, he_ids,
                                     n2e_w1, n2e_b1, n2e_lng, n2e_lnb, n2e_w2, n2e_b2);
    k_e2n<<<MM / ROWS, 256, smem2>>>(node_ids, he_ids, he_attr, he_count,
                                     e2n_w1, e2n_b1, e2n_lng, e2n_lnb, e2n_w2, e2n_b2);
    k_final<<<(NN + 7) / 8, 256>>>(x, ln_g, ln_b, out);
}